// round 8
// baseline (speedup 1.0000x reference)
#include <cuda_runtime.h>

#define DIM    4096
#define RANK   32
#define NROWS  32          // B(4) * 8 edited rows
#define NDOTS  64          // per row: 32 src + 32 proj
#define NSPLIT 4           // K-dim split per dot

// Partial dot products: [row j][dot di][split]
__device__ float g_part[NROWS * NDOTS * NSPLIT];

// ---------------------------------------------------------------------------
// dots: one warp per (edited row j, dot di, K-split). 1024 CTAs. (R5, proven)
// ---------------------------------------------------------------------------
__global__ __launch_bounds__(256) void dots_kernel(
    const float* __restrict__ hs,
    const float* __restrict__ Wsrc_p, const float* __restrict__ Wproj_p,
    const float* __restrict__ Wsrc_s, const float* __restrict__ Wproj_s,
    const int* __restrict__ offsets, const int* __restrict__ seqlens)
{
    const int warp = threadIdx.x >> 5;
    const int lane = threadIdx.x & 31;
    const int gw = blockIdx.x * 8 + warp;     // 0..8191
    const int j     = gw >> 8;                // 0..31
    const int di    = (gw >> 2) & 63;         // 0..63
    const int split = gw & 3;                 // 0..3

    const int b = j >> 3;
    const int slot = j & 7;
    int pos;
    const float *Wsrc, *Wproj;
    if (slot < 4) {
        pos = offsets[b] + slot;
        Wsrc = Wsrc_p; Wproj = Wproj_p;
    } else {
        pos = offsets[b] + seqlens[b] - 8 + slot;
        Wsrc = Wsrc_s; Wproj = Wproj_s;
    }

    const float4* x4 = (const float4*)(hs + ((long)b * 4096 + pos) * DIM);
    const float4* W4 = (const float4*)((di < RANK)
                           ? (Wsrc  + (long)di * DIM)
                           : (Wproj + (long)(di - RANK) * DIM));

    const int k0 = split * (DIM / 4 / NSPLIT);   // 256 float4 per split
    float acc = 0.f;
    #pragma unroll
    for (int k = 0; k < 8; k++) {
        const int i = k0 + lane + k * 32;
        float4 w  = W4[i];
        float4 xv = x4[i];
        acc += w.x * xv.x + w.y * xv.y + w.z * xv.z + w.w * xv.w;
    }
    #pragma unroll
    for (int o = 16; o > 0; o >>= 1)
        acc += __shfl_xor_sync(0xffffffff, acc, o);
    if (lane == 0) g_part[(j * NDOTS + di) * NSPLIT + split] = acc;
}

// ---------------------------------------------------------------------------
// copy: one CTA per row; edited rows exit early (owned by apply_kernel).
// Exact R5 copy shape (compiler-scheduled 4x float4 batch, 73.7% DRAM).
// ---------------------------------------------------------------------------
__global__ __launch_bounds__(256) void copy_kernel(
    const float* __restrict__ hs,
    const int* __restrict__ offsets, const int* __restrict__ seqlens,
    float* __restrict__ out)
{
    const int row = blockIdx.x;            // 0..16383
    const int tid = threadIdx.x;
    const int b = row >> 12;
    const int t = row & 4095;
    const int off = offsets[b];
    const int seq = seqlens[b];

    if (((unsigned)(t - off) < 4u) | ((unsigned)(t - (off + seq - 4)) < 4u))
        return;   // edited row

    const long base = (long)row * DIM;
    const float4* x4 = (const float4*)(hs + base);
    float4*       o4 = (float4*)(out + base);
    #pragma unroll
    for (int k = 0; k < 4; k++) {
        int i = tid + k * 256;
        o4[i] = x4[i];
    }
}

// ---------------------------------------------------------------------------
// apply: one CTA per edited row; reduces g_part, writes x + s·Wproj.
// ---------------------------------------------------------------------------
__global__ __launch_bounds__(256) void apply_kernel(
    const float* __restrict__ hs,
    const float* __restrict__ bsrc_p, const float* __restrict__ Wproj_p,
    const float* __restrict__ bsrc_s, const float* __restrict__ Wproj_s,
    const int* __restrict__ offsets, const int* __restrict__ seqlens,
    float* __restrict__ out)
{
    const int j = blockIdx.x;              // 0..31
    const int tid = threadIdx.x;
    const int b = j >> 3;
    const int slot = j & 7;
    int pos;
    const float *bias, *Wproj;
    if (slot < 4) {
        pos = offsets[b] + slot;
        bias = bsrc_p; Wproj = Wproj_p;
    } else {
        pos = offsets[b] + seqlens[b] - 8 + slot;
        bias = bsrc_s; Wproj = Wproj_s;
    }

    __shared__ float s[RANK];
    if (tid < RANK) {
        const float* pp = &g_part[(j * NDOTS + tid) * NSPLIT];
        const float* qq = &g_part[(j * NDOTS + RANK + tid) * NSPLIT];
        float src  = pp[0] + pp[1] + pp[2] + pp[3] + bias[tid];
        float proj = qq[0] + qq[1] + qq[2] + qq[3];
        s[tid] = (src > 0.f ? src : 0.f) - proj;
    }
    __syncthreads();

    const long base = ((long)b * 4096 + pos) * DIM;
    const float4* x4 = (const float4*)(hs + base);
    float4*       o4 = (float4*)(out + base);
    #pragma unroll
    for (int k = 0; k < 4; k++) {
        int i = tid + k * 256;
        float4 acc = x4[i];
        #pragma unroll
        for (int r = 0; r < RANK; r++) {
            float4 w = ((const float4*)(Wproj + (long)r * DIM))[i];
            float sr = s[r];
            acc.x += sr * w.x;
            acc.y += sr * w.y;
            acc.z += sr * w.z;
            acc.w += sr * w.w;
        }
        o4[i] = acc;
    }
}

extern "C" void kernel_launch(void* const* d_in, const int* in_sizes, int n_in,
                              void* d_out, int out_size) {
    const float* hs      = (const float*)d_in[0];
    const float* Wsrc_p  = (const float*)d_in[1];
    const float* bsrc_p  = (const float*)d_in[2];
    const float* Wproj_p = (const float*)d_in[3];
    const float* Wsrc_s  = (const float*)d_in[4];
    const float* bsrc_s  = (const float*)d_in[5];
    const float* Wproj_s = (const float*)d_in[6];
    const int*   offsets = (const int*)d_in[7];
    const int*   seqlens = (const int*)d_in[8];
    float* out = (float*)d_out;

    // One-time host-object setup (no device memory involved).
    static cudaStream_t side = nullptr;
    static cudaEvent_t ev_fork = nullptr, ev_join = nullptr;
    static bool tried = false;
    if (!tried) {
        tried = true;
        if (cudaStreamCreateWithFlags(&side, cudaStreamNonBlocking) != cudaSuccess)
            side = nullptr;
        if (side) {
            if (cudaEventCreateWithFlags(&ev_fork, cudaEventDisableTiming) != cudaSuccess ||
                cudaEventCreateWithFlags(&ev_join, cudaEventDisableTiming) != cudaSuccess) {
                side = nullptr;
            }
        }
    }

    const int nrows = out_size / DIM;      // 16384

    if (side) {
        // Fork: side stream runs dots -> apply, concurrent with copy.
        cudaEventRecord(ev_fork, 0);
        cudaStreamWaitEvent(side, ev_fork, 0);

        dots_kernel<<<1024, 256, 0, side>>>(hs, Wsrc_p, Wproj_p, Wsrc_s, Wproj_s,
                                            offsets, seqlens);
        apply_kernel<<<NROWS, 256, 0, side>>>(hs, bsrc_p, Wproj_p, bsrc_s, Wproj_s,
                                              offsets, seqlens, out);

        copy_kernel<<<nrows, 256>>>(hs, offsets, seqlens, out);

        // Join
        cudaEventRecord(ev_join, side);
        cudaStreamWaitEvent(0, ev_join, 0);
    } else {
        // Serialized fallback (R5 behavior)
        dots_kernel<<<1024, 256>>>(hs, Wsrc_p, Wproj_p, Wsrc_s, Wproj_s,
                                   offsets, seqlens);
        copy_kernel<<<nrows, 256>>>(hs, offsets, seqlens, out);
        apply_kernel<<<NROWS, 256>>>(hs, bsrc_p, Wproj_p, bsrc_s, Wproj_s,
                                     offsets, seqlens, out);
    }
}